// round 15
// baseline (speedup 1.0000x reference)
#include <cuda_runtime.h>
#include <math.h>

// Problem constants (validated against in_sizes at launch).
#define NMAX 20000
#define EMAX 640000
#define CAPB 192   // per-node edge bucket capacity (deg ~ Poisson(32), max ~56)
#define SCAP 384   // edge chunk per node in fused kernels (multiple of 4)
#define SROW 388   // padded score row stride

// ---------------- device scratch (no allocations allowed) ----------------
__device__ int   g_is64;
__device__ float g_easum[NMAX];
__device__ int   g_cnt[NMAX];
__device__ int   g_bsrc[NMAX * CAPB];   // per-dst bucketed src ids
__device__ float g_bea[NMAX * CAPB];    // per-dst bucketed edge attrs
__device__ float g_xl1[NMAX * 256];
__device__ float g_xr1[NMAX * 256];
__device__ float g_h1[NMAX * 256];
__device__ float g_xl2[NMAX * 128];
__device__ float g_xr2[NMAX * 128];
__device__ float g_pool[128];

// Device-side scratch selector (avoids any host-side symbol queries).
__device__ __forceinline__ float* buf_sel(int code) {
    switch (code) {
        case 0:  return g_xl1;
        case 1:  return g_xr1;
        case 2:  return g_h1;
        case 3:  return g_xl2;
        default: return g_xr2;
    }
}

// ------- zero accumulators + int64 layout detect (1 launch) --------------
__global__ void detect_init_kernel(const int* __restrict__ raw, int n, int E) {
    int i = blockIdx.x * blockDim.x + threadIdx.x;
    if (i < n) {
        g_easum[i] = 0.f;
        g_cnt[i]   = 0;
    }
    if (i < 128) g_pool[i] = 0.f;
    if (blockIdx.x == 0 && threadIdx.x < 32) {
        int nz = 0;
        int lim = (E < 64) ? E : 64;
        for (int k = threadIdx.x; k < lim; k += 32)
            if (raw[2 * k + 1] != 0) nz = 1;
        nz = __any_sync(0xffffffffu, nz);
        if (threadIdx.x == 0) g_is64 = nz ? 0 : 1;
    }
}

// Bucket (src, ea) by dst; accumulate edge_attr sums.
__global__ void extract_kernel(const int* __restrict__ raw,
                               const float* __restrict__ ea, int E) {
    int e = blockIdx.x * blockDim.x + threadIdx.x;
    if (e >= E) return;
    int is64 = g_is64;
    int s = is64 ? raw[2 * e]       : raw[e];
    int d = is64 ? raw[2 * (E + e)] : raw[E + e];
    float v = ea[e];
    int pos = atomicAdd(&g_cnt[d], 1);
    if (pos < CAPB) {
        g_bsrc[d * CAPB + pos] = s;
        g_bea[d * CAPB + pos]  = v;
    }
    atomicAdd(&g_easum[d], v);
}

// ---- fp32 SGEMM 128x128, 8x8/thread, k-panel 8, double-buffered smem ----
__global__ void __launch_bounds__(256, 2)
gemm_bias_dual(const float* __restrict__ Ain, int Acode,
               const float* __restrict__ W0, const float* __restrict__ b0, int C0code,
               const float* __restrict__ W1, const float* __restrict__ b1, int C1code,
               int M, int K, int Nn) {
    const float* A = (Acode >= 0) ? buf_sel(Acode) : Ain;
    const float* W    = (blockIdx.z == 0) ? W0 : W1;
    const float* bias = (blockIdx.z == 0) ? b0 : b1;
    float* C = buf_sel(blockIdx.z == 0 ? C0code : C1code);

    __shared__ __align__(16) float As[2][8][132];   // transposed A panel
    __shared__ __align__(16) float Bs[2][8][128];

    const int tid = threadIdx.x;
    const int tx = tid & 15, ty = tid >> 4;
    const int tm0 = ty * 8, tn0 = tx * 8;
    const int row0 = blockIdx.x * 128, col0 = blockIdx.y * 128;

    const int arow = tid >> 1;            // 0..127
    const int acol = (tid & 1) * 4;       // 0 or 4
    const int b_r = tid >> 5;             // 0..7
    const int b_c = (tid & 31) * 4;       // 0..124

    const int a_gr = row0 + arow;
    const bool a_ok = (a_gr < M);
    const int P = K >> 3;

    float acc[8][8];
    #pragma unroll
    for (int i = 0; i < 8; i++)
        #pragma unroll
        for (int j = 0; j < 8; j++) acc[i][j] = 0.f;

    // preload panel 0
    {
        float4 av = make_float4(0.f, 0.f, 0.f, 0.f);
        if (a_ok) av = *(const float4*)&A[(size_t)a_gr * K + acol];
        float4 bv = *(const float4*)&W[(size_t)b_r * Nn + col0 + b_c];
        As[0][acol + 0][arow] = av.x;
        As[0][acol + 1][arow] = av.y;
        As[0][acol + 2][arow] = av.z;
        As[0][acol + 3][arow] = av.w;
        *(float4*)&Bs[0][b_r][b_c] = bv;
    }
    __syncthreads();

    for (int p = 0; p < P; p++) {
        const int cur = p & 1;
        const bool more = (p + 1 < P);
        float4 av_n = make_float4(0.f, 0.f, 0.f, 0.f), bv_n;
        if (more) {
            int k0 = (p + 1) * 8;
            if (a_ok) av_n = *(const float4*)&A[(size_t)a_gr * K + k0 + acol];
            bv_n = *(const float4*)&W[(size_t)(k0 + b_r) * Nn + col0 + b_c];
        }

        #pragma unroll
        for (int kk = 0; kk < 8; kk++) {
            float a[8], b[8];
            *(float4*)&a[0] = *(const float4*)&As[cur][kk][tm0];
            *(float4*)&a[4] = *(const float4*)&As[cur][kk][tm0 + 4];
            *(float4*)&b[0] = *(const float4*)&Bs[cur][kk][tn0];
            *(float4*)&b[4] = *(const float4*)&Bs[cur][kk][tn0 + 4];
            #pragma unroll
            for (int i = 0; i < 8; i++)
                #pragma unroll
                for (int j = 0; j < 8; j++)
                    acc[i][j] += a[i] * b[j];
        }

        if (more) {
            const int nxt = cur ^ 1;
            As[nxt][acol + 0][arow] = av_n.x;
            As[nxt][acol + 1][arow] = av_n.y;
            As[nxt][acol + 2][arow] = av_n.z;
            As[nxt][acol + 3][arow] = av_n.w;
            *(float4*)&Bs[nxt][b_r][b_c] = bv_n;
        }
        __syncthreads();
    }

    float bcache[8];
    #pragma unroll
    for (int j = 0; j < 8; j++) bcache[j] = bias[col0 + tn0 + j];
    #pragma unroll
    for (int i = 0; i < 8; i++) {
        int gr = row0 + tm0 + i;
        if (gr >= M) continue;
        float4 v0 = make_float4(acc[i][0] + bcache[0], acc[i][1] + bcache[1],
                                acc[i][2] + bcache[2], acc[i][3] + bcache[3]);
        float4 v1 = make_float4(acc[i][4] + bcache[4], acc[i][5] + bcache[5],
                                acc[i][6] + bcache[6], acc[i][7] + bcache[7]);
        *(float4*)&C[(size_t)gr * Nn + col0 + tn0]     = v0;
        *(float4*)&C[(size_t)gr * Nn + col0 + tn0 + 4] = v1;
    }
}

// leaky-relu + att partial score over 8 channels (two float4 groups)
__device__ __forceinline__ float score8(
    float4 a0, float4 a1, float4 xr0, float4 xr1,
    float4 W0, float4 W1, float4 A0, float4 A1, float v) {
    float a = a0.x + xr0.x + v * W0.x; a = fmaxf(a,0.f) + 0.2f*fminf(a,0.f);
    float b = a0.y + xr0.y + v * W0.y; b = fmaxf(b,0.f) + 0.2f*fminf(b,0.f);
    float c = a0.z + xr0.z + v * W0.z; c = fmaxf(c,0.f) + 0.2f*fminf(c,0.f);
    float g = a0.w + xr0.w + v * W0.w; g = fmaxf(g,0.f) + 0.2f*fminf(g,0.f);
    float p = a*A0.x + b*A0.y + c*A0.z + g*A0.w;
    a = a1.x + xr1.x + v * W1.x; a = fmaxf(a,0.f) + 0.2f*fminf(a,0.f);
    b = a1.y + xr1.y + v * W1.y; b = fmaxf(b,0.f) + 0.2f*fminf(b,0.f);
    c = a1.z + xr1.z + v * W1.z; c = fmaxf(c,0.f) + 0.2f*fminf(c,0.f);
    g = a1.w + xr1.w + v * W1.w; g = fmaxf(g,0.f) + 0.2f*fminf(g,0.f);
    return p + a*A1.x + b*A1.y + c*A1.z + g*A1.w;
}

// leaky-relu + att partial score over 4 channels
__device__ __forceinline__ float score4(float4 l, float4 xr, float4 Wv,
                                        float4 Av, float v) {
    float a = l.x + xr.x + v * Wv.x; a = fmaxf(a,0.f) + 0.2f*fminf(a,0.f);
    float b = l.y + xr.y + v * Wv.y; b = fmaxf(b,0.f) + 0.2f*fminf(b,0.f);
    float c = l.z + xr.z + v * Wv.z; c = fmaxf(c,0.f) + 0.2f*fminf(c,0.f);
    float g = l.w + xr.w + v * Wv.w; g = fmaxf(g,0.f) + 0.2f*fminf(g,0.f);
    return a*Av.x + b*Av.y + c*Av.z + g*Av.w;
}

// ===== fused layer-1: per-node block, parallel scoring into smem =========
__global__ void __launch_bounds__(256)
fused1_kernel(const float* __restrict__ We, const float* __restrict__ att,
              const float* __restrict__ bias, const float* __restrict__ ea) {
    __shared__ __align__(16) float s[8 * SROW];
    __shared__ __align__(16) int   ssrc[SCAP];
    __shared__ float sea[SCAP];
    __shared__ float mh[8], sumh[8];

    const int j = blockIdx.x;
    const int cntj = g_cnt[j];
    const int dreal = min(cntj, CAPB);
    const int d = dreal + 1;               // + self loop
    const int off = j * CAPB;
    const int t = threadIdx.x;
    const int warp = t >> 5, lane = t & 31;
    const float eal = g_easum[j] / fmaxf((float)cntj, 1.0f);
    const int jofs = j * 256;

    if (t < 8) { mh[t] = -1e30f; sumh[t] = 0.f; }

    const int c0 = lane * 8;
    const float4 W0 = *(const float4*)&We[c0],  W1 = *(const float4*)&We[c0 + 4];
    const float4 A0 = *(const float4*)&att[c0], A1 = *(const float4*)&att[c0 + 4];
    const float4 xr0 = *(const float4*)&g_xr1[(size_t)jofs + c0];
    const float4 xr1 = *(const float4*)&g_xr1[(size_t)jofs + c0 + 4];

    float accv = 0.f;   // phase-C channel c = warp*32 + lane

    for (int cs = 0; cs < d; cs += SCAP) {
        const int cl = min(SCAP, d - cs);
        const int cl4 = (cl + 3) & ~3;
        for (int i = t; i < cl4; i += 256) {
            int ge = cs + i;
            if (ge < dreal) {
                ssrc[i] = g_bsrc[off + ge] << 8;   // *256 prescale (coalesced)
                sea[i]  = g_bea[off + ge];
            } else {
                ssrc[i] = jofs;                    // self loop / pad
                sea[i]  = eal;
            }
        }
        __syncthreads();

        // ---- phase A: 4 edges in flight per warp ----------------------
        for (int e = warp; e < cl; e += 32) {
            int e1 = e + 8, e2 = e + 16, e3 = e + 24;
            bool h1 = (e1 < cl), h2 = (e2 < cl), h3 = (e3 < cl);
            int   o0v = ssrc[e];
            int   o1v = h1 ? ssrc[e1] : o0v;
            int   o2v = h2 ? ssrc[e2] : o0v;
            int   o3v = h3 ? ssrc[e3] : o0v;
            float v0 = sea[e];
            float v1 = h1 ? sea[e1] : v0;
            float v2 = h2 ? sea[e2] : v0;
            float v3 = h3 ? sea[e3] : v0;
            // issue all 8 row loads before compute
            float4 r0a = *(const float4*)&g_xl1[o0v + c0];
            float4 r0b = *(const float4*)&g_xl1[o0v + c0 + 4];
            float4 r1a = *(const float4*)&g_xl1[o1v + c0];
            float4 r1b = *(const float4*)&g_xl1[o1v + c0 + 4];
            float4 r2a = *(const float4*)&g_xl1[o2v + c0];
            float4 r2b = *(const float4*)&g_xl1[o2v + c0 + 4];
            float4 r3a = *(const float4*)&g_xl1[o3v + c0];
            float4 r3b = *(const float4*)&g_xl1[o3v + c0 + 4];
            float p0 = score8(r0a, r0b, xr0, xr1, W0, W1, A0, A1, v0);
            float p1 = score8(r1a, r1b, xr0, xr1, W0, W1, A0, A1, v1);
            float p2 = score8(r2a, r2b, xr0, xr1, W0, W1, A0, A1, v2);
            float p3 = score8(r3a, r3b, xr0, xr1, W0, W1, A0, A1, v3);
            p0 += __shfl_xor_sync(0xffffffffu, p0, 1);
            p1 += __shfl_xor_sync(0xffffffffu, p1, 1);
            p2 += __shfl_xor_sync(0xffffffffu, p2, 1);
            p3 += __shfl_xor_sync(0xffffffffu, p3, 1);
            p0 += __shfl_xor_sync(0xffffffffu, p0, 2);
            p1 += __shfl_xor_sync(0xffffffffu, p1, 2);
            p2 += __shfl_xor_sync(0xffffffffu, p2, 2);
            p3 += __shfl_xor_sync(0xffffffffu, p3, 2);
            if ((lane & 3) == 0) {
                int hrow = (lane >> 2) * SROW;
                s[hrow + e] = p0;
                if (h1) s[hrow + e1] = p1;
                if (h2) s[hrow + e2] = p2;
                if (h3) s[hrow + e3] = p3;
            }
        }
        __syncthreads();

        // ---- phase B: per-head chunk max/sum, scores -> weights --------
        const int h = warp;
        float* sw = s + h * SROW;
        float cmx = -1e30f;
        for (int e = lane; e < cl; e += 32) cmx = fmaxf(cmx, sw[e]);
        #pragma unroll
        for (int o = 16; o; o >>= 1)
            cmx = fmaxf(cmx, __shfl_xor_sync(0xffffffffu, cmx, o));
        float m_o = mh[h];
        float nm = fmaxf(m_o, cmx);
        float csum = 0.f;
        for (int e = lane; e < cl; e += 32) {
            float w = __expf(sw[e] - nm);
            sw[e] = w;
            csum += w;
        }
        for (int e = cl + lane; e < cl4; e += 32) sw[e] = 0.f;  // pad
        #pragma unroll
        for (int o = 16; o; o >>= 1) csum += __shfl_xor_sync(0xffffffffu, csum, o);
        float fac = __expf(m_o - nm);
        if (lane == 0) { sumh[h] = sumh[h] * fac + csum; mh[h] = nm; }
        __syncwarp();

        // ---- phase C: vectorized gather (broadcast float4/int4) --------
        const float* xbase = g_xl1 + h * 32 + lane;
        float p0 = 0.f, p1 = 0.f, p2 = 0.f, p3 = 0.f;
        for (int e = 0; e < cl4; e += 4) {
            float4 wv = *(const float4*)&sw[e];
            int4   iv = *(const int4*)&ssrc[e];
            p0 += wv.x * xbase[iv.x];
            p1 += wv.y * xbase[iv.y];
            p2 += wv.z * xbase[iv.z];
            p3 += wv.w * xbase[iv.w];
        }
        accv = accv * fac + ((p0 + p1) + (p2 + p3));
        __syncthreads();
    }

    const int h = warp;
    float inv = 1.0f / (sumh[h] + 1e-16f);
    int c = h * 32 + lane;
    g_h1[(size_t)j * 256 + c] = fmaxf(accv * inv + bias[c], 0.f);
}

// ===== fused layer-2: per-node block (128 thr), single head ==============
__global__ void __launch_bounds__(128)
fused2_kernel(const float* __restrict__ We, const float* __restrict__ att,
              const float* __restrict__ bias, const float* __restrict__ ea) {
    __shared__ __align__(16) float s[SCAP];
    __shared__ __align__(16) int   ssrc[SCAP];
    __shared__ float sea[SCAP];
    __shared__ float red[4];
    __shared__ float m_run_s, sum_run_s, nm_s, fac_s;

    const int j = blockIdx.x;
    const int cntj = g_cnt[j];
    const int dreal = min(cntj, CAPB);
    const int d = dreal + 1;               // + self loop
    const int off = j * CAPB;
    const int t = threadIdx.x;
    const int warp = t >> 5, lane = t & 31;
    const float eal = g_easum[j] / fmaxf((float)cntj, 1.0f);
    const int jofs = j * 128;

    if (t == 0) { m_run_s = -1e30f; sum_run_s = 0.f; }

    const int c0 = lane * 4;
    const float4 Wv = *(const float4*)&We[c0];
    const float4 Av = *(const float4*)&att[c0];
    const float4 xr = *(const float4*)&g_xr2[(size_t)jofs + c0];

    float accv = 0.f;   // channel = t

    for (int cs = 0; cs < d; cs += SCAP) {
        const int cl = min(SCAP, d - cs);
        const int cl4 = (cl + 3) & ~3;
        for (int i = t; i < cl4; i += 128) {
            int ge = cs + i;
            if (ge < dreal) {
                ssrc[i] = g_bsrc[off + ge] << 7;   // *128 prescale (coalesced)
                sea[i]  = g_bea[off + ge];
            } else {
                ssrc[i] = jofs;
                sea[i]  = eal;
            }
        }
        __syncthreads();

        // phase A: 4 edges in flight per warp (stride 16)
        for (int e = warp; e < cl; e += 16) {
            int e1 = e + 4, e2 = e + 8, e3 = e + 12;
            bool h1 = (e1 < cl), h2 = (e2 < cl), h3 = (e3 < cl);
            int   o0v = ssrc[e];
            int   o1v = h1 ? ssrc[e1] : o0v;
            int   o2v = h2 ? ssrc[e2] : o0v;
            int   o3v = h3 ? ssrc[e3] : o0v;
            float v0 = sea[e];
            float v1 = h1 ? sea[e1] : v0;
            float v2 = h2 ? sea[e2] : v0;
            float v3 = h3 ? sea[e3] : v0;
            float4 l0 = *(const float4*)&g_xl2[o0v + c0];
            float4 l1 = *(const float4*)&g_xl2[o1v + c0];
            float4 l2 = *(const float4*)&g_xl2[o2v + c0];
            float4 l3 = *(const float4*)&g_xl2[o3v + c0];
            float p0 = score4(l0, xr, Wv, Av, v0);
            float p1 = score4(l1, xr, Wv, Av, v1);
            float p2 = score4(l2, xr, Wv, Av, v2);
            float p3 = score4(l3, xr, Wv, Av, v3);
            #pragma unroll
            for (int o = 16; o; o >>= 1) {
                p0 += __shfl_xor_sync(0xffffffffu, p0, o);
                p1 += __shfl_xor_sync(0xffffffffu, p1, o);
                p2 += __shfl_xor_sync(0xffffffffu, p2, o);
                p3 += __shfl_xor_sync(0xffffffffu, p3, o);
            }
            if (lane == 0) {
                s[e] = p0;
                if (h1) s[e1] = p1;
                if (h2) s[e2] = p2;
                if (h3) s[e3] = p3;
            }
        }
        __syncthreads();

        // phase B: block max
        float cmx = -1e30f;
        for (int e = t; e < cl; e += 128) cmx = fmaxf(cmx, s[e]);
        #pragma unroll
        for (int o = 16; o; o >>= 1)
            cmx = fmaxf(cmx, __shfl_xor_sync(0xffffffffu, cmx, o));
        if (lane == 0) red[warp] = cmx;
        __syncthreads();
        if (t == 0) {
            float M = fmaxf(fmaxf(red[0], red[1]), fmaxf(red[2], red[3]));
            float nm = fmaxf(m_run_s, M);
            nm_s = nm;
            fac_s = __expf(m_run_s - nm);
            m_run_s = nm;
        }
        __syncthreads();
        float nm = nm_s;
        float csum = 0.f;
        for (int e = t; e < cl; e += 128) {
            float w = __expf(s[e] - nm);
            s[e] = w;
            csum += w;
        }
        for (int e = cl + t; e < cl4; e += 128) s[e] = 0.f;
        #pragma unroll
        for (int o = 16; o; o >>= 1) csum += __shfl_xor_sync(0xffffffffu, csum, o);
        if (lane == 0) red[warp] = csum;
        __syncthreads();
        if (t == 0)
            sum_run_s = sum_run_s * fac_s + (red[0] + red[1] + red[2] + red[3]);
        float fac = fac_s;
        __syncthreads();   // weights visible before gather

        // phase C: vectorized gather (broadcast float4/int4), channel = t
        const float* xbase = g_xl2 + t;
        float p0 = 0.f, p1 = 0.f, p2 = 0.f, p3 = 0.f;
        for (int e = 0; e < cl4; e += 4) {
            float4 wv = *(const float4*)&s[e];
            int4   iv = *(const int4*)&ssrc[e];
            p0 += wv.x * xbase[iv.x];
            p1 += wv.y * xbase[iv.y];
            p2 += wv.z * xbase[iv.z];
            p3 += wv.w * xbase[iv.w];
        }
        accv = accv * fac + ((p0 + p1) + (p2 + p3));
        __syncthreads();
    }

    float inv = 1.0f / (sum_run_s + 1e-16f);
    float val = fmaxf(accv * inv + bias[t], 0.f);
    atomicAdd(&g_pool[t], val);
}

// ---------------- final: mean, softmax, sigmoid(alpha) -------------------
__global__ void final_kernel(const float* __restrict__ alpha_in,
                             float* __restrict__ out, int out_size, float invN) {
    __shared__ float sh[128];
    int t = threadIdx.x;
    float v = g_pool[t] * invN;
    sh[t] = v;
    __syncthreads();
    for (int o = 64; o; o >>= 1) {
        if (t < o) sh[t] = fmaxf(sh[t], sh[t + o]);
        __syncthreads();
    }
    float mx = sh[0];
    __syncthreads();
    float e = __expf(v - mx);
    sh[t] = e;
    __syncthreads();
    for (int o = 64; o; o >>= 1) {
        if (t < o) sh[t] += sh[t + o];
        __syncthreads();
    }
    float s = sh[0];
    out[t] = e / s;
    if (t == 0 && out_size > 128)
        out[128] = 1.0f / (1.0f + __expf(-alpha_in[0]));
}

// -------------------------------------------------------------------------
extern "C" void kernel_launch(void* const* d_in, const int* in_sizes, int n_in,
                              void* d_out, int out_size) {
    (void)n_in;
    const float* x     = (const float*)d_in[0];
    const int*   eidx  = (const int*)d_in[1];   // int32 or int64 (detected)
    const float* ea    = (const float*)d_in[2];
    const float* W1l   = (const float*)d_in[3];
    const float* b1l   = (const float*)d_in[4];
    const float* W1r   = (const float*)d_in[5];
    const float* b1r   = (const float*)d_in[6];
    const float* We1   = (const float*)d_in[7];
    const float* att1  = (const float*)d_in[8];
    const float* bias1 = (const float*)d_in[9];
    const float* W2l   = (const float*)d_in[10];
    const float* b2l   = (const float*)d_in[11];
    const float* W2r   = (const float*)d_in[12];
    const float* b2r   = (const float*)d_in[13];
    const float* We2   = (const float*)d_in[14];
    const float* att2  = (const float*)d_in[15];
    const float* bias2 = (const float*)d_in[16];
    const float* alpha = (const float*)d_in[17];
    float* out = (float*)d_out;

    int N = in_sizes[0] / 128;
    if (N > NMAX) N = NMAX;
    int E = in_sizes[1] / 2;
    if (E > EMAX) E = EMAX;

    int mb = (N + 127) / 128;

    detect_init_kernel<<<(N + 255) / 256, 256>>>(eidx, N, E);   // 1
    gemm_bias_dual<<<dim3(mb, 2, 2), 256>>>(x, -1, W1l, b1l, 0, W1r, b1r, 1,
                                            N, 128, 256);      // 2
    extract_kernel<<<(E + 255) / 256, 256>>>(eidx, ea, E);      // 3

    // layer 1: fused score+softmax+aggregate (per node) — profiled slot 4
    fused1_kernel<<<N, 256>>>(We1, att1, bias1, ea);            // 4

    // layer 2
    gemm_bias_dual<<<dim3(mb, 1, 2), 256>>>(nullptr, 2, W2l, b2l, 3, W2r, b2r, 4,
                                            N, 256, 128);      // 5
    fused2_kernel<<<N, 128>>>(We2, att2, bias2, ea);            // 6

    // pooled softmax + sigmoid(alpha)
    final_kernel<<<1, 128>>>(alpha, out, out_size, 1.0f / (float)N); // 7
}

// round 16
// speedup vs baseline: 1.5814x; 1.5814x over previous
#include <cuda_runtime.h>
#include <math.h>

// Problem constants (validated against in_sizes at launch).
#define NMAX 20000
#define EMAX 640000
#define CAPB 192   // per-node edge bucket capacity (deg ~ Poisson(32), max ~56)
#define SCAP 384   // edge chunk per node in fused kernels (multiple of 4)
#define SROW 388   // padded score row stride

// ---------------- device scratch (no allocations allowed) ----------------
__device__ int   g_is64;
__device__ float g_easum[NMAX];
__device__ int   g_cnt[NMAX];
__device__ int   g_bsrc[NMAX * CAPB];   // per-dst bucketed src ids
__device__ float g_bea[NMAX * CAPB];    // per-dst bucketed edge attrs
__device__ float g_xl1[NMAX * 256];
__device__ float g_xr1[NMAX * 256];
__device__ float g_h1[NMAX * 256];
__device__ float g_xl2[NMAX * 128];
__device__ float g_xr2[NMAX * 128];
__device__ float g_pool[128];

// Device-side scratch selector (avoids any host-side symbol queries).
__device__ __forceinline__ float* buf_sel(int code) {
    switch (code) {
        case 0:  return g_xl1;
        case 1:  return g_xr1;
        case 2:  return g_h1;
        case 3:  return g_xl2;
        default: return g_xr2;
    }
}

// ------- zero accumulators + int64 layout detect (1 launch) --------------
__global__ void detect_init_kernel(const int* __restrict__ raw, int n, int E) {
    int i = blockIdx.x * blockDim.x + threadIdx.x;
    if (i < n) {
        g_easum[i] = 0.f;
        g_cnt[i]   = 0;
    }
    if (i < 128) g_pool[i] = 0.f;
    if (blockIdx.x == 0 && threadIdx.x < 32) {
        int nz = 0;
        int lim = (E < 64) ? E : 64;
        for (int k = threadIdx.x; k < lim; k += 32)
            if (raw[2 * k + 1] != 0) nz = 1;
        nz = __any_sync(0xffffffffu, nz);
        if (threadIdx.x == 0) g_is64 = nz ? 0 : 1;
    }
}

// Bucket (src, ea) by dst; accumulate edge_attr sums.
__global__ void extract_kernel(const int* __restrict__ raw,
                               const float* __restrict__ ea, int E) {
    int e = blockIdx.x * blockDim.x + threadIdx.x;
    if (e >= E) return;
    int is64 = g_is64;
    int s = is64 ? raw[2 * e]       : raw[e];
    int d = is64 ? raw[2 * (E + e)] : raw[E + e];
    float v = ea[e];
    int pos = atomicAdd(&g_cnt[d], 1);
    if (pos < CAPB) {
        g_bsrc[d * CAPB + pos] = s;
        g_bea[d * CAPB + pos]  = v;
    }
    atomicAdd(&g_easum[d], v);
}

// ---- fp32 SGEMM 128x128, 8x8/thread, k-panel 8, double-buffered smem ----
__global__ void __launch_bounds__(256, 2)
gemm_bias_dual(const float* __restrict__ Ain, int Acode,
               const float* __restrict__ W0, const float* __restrict__ b0, int C0code,
               const float* __restrict__ W1, const float* __restrict__ b1, int C1code,
               int M, int K, int Nn) {
    const float* A = (Acode >= 0) ? buf_sel(Acode) : Ain;
    const float* W    = (blockIdx.z == 0) ? W0 : W1;
    const float* bias = (blockIdx.z == 0) ? b0 : b1;
    float* C = buf_sel(blockIdx.z == 0 ? C0code : C1code);

    __shared__ __align__(16) float As[2][8][132];   // transposed A panel
    __shared__ __align__(16) float Bs[2][8][128];

    const int tid = threadIdx.x;
    const int tx = tid & 15, ty = tid >> 4;
    const int tm0 = ty * 8, tn0 = tx * 8;
    const int row0 = blockIdx.x * 128, col0 = blockIdx.y * 128;

    const int arow = tid >> 1;            // 0..127
    const int acol = (tid & 1) * 4;       // 0 or 4
    const int b_r = tid >> 5;             // 0..7
    const int b_c = (tid & 31) * 4;       // 0..124

    const int a_gr = row0 + arow;
    const bool a_ok = (a_gr < M);
    const int P = K >> 3;

    float acc[8][8];
    #pragma unroll
    for (int i = 0; i < 8; i++)
        #pragma unroll
        for (int j = 0; j < 8; j++) acc[i][j] = 0.f;

    // preload panel 0
    {
        float4 av = make_float4(0.f, 0.f, 0.f, 0.f);
        if (a_ok) av = *(const float4*)&A[(size_t)a_gr * K + acol];
        float4 bv = *(const float4*)&W[(size_t)b_r * Nn + col0 + b_c];
        As[0][acol + 0][arow] = av.x;
        As[0][acol + 1][arow] = av.y;
        As[0][acol + 2][arow] = av.z;
        As[0][acol + 3][arow] = av.w;
        *(float4*)&Bs[0][b_r][b_c] = bv;
    }
    __syncthreads();

    for (int p = 0; p < P; p++) {
        const int cur = p & 1;
        const bool more = (p + 1 < P);
        float4 av_n = make_float4(0.f, 0.f, 0.f, 0.f), bv_n;
        if (more) {
            int k0 = (p + 1) * 8;
            if (a_ok) av_n = *(const float4*)&A[(size_t)a_gr * K + k0 + acol];
            bv_n = *(const float4*)&W[(size_t)(k0 + b_r) * Nn + col0 + b_c];
        }

        #pragma unroll
        for (int kk = 0; kk < 8; kk++) {
            float a[8], b[8];
            *(float4*)&a[0] = *(const float4*)&As[cur][kk][tm0];
            *(float4*)&a[4] = *(const float4*)&As[cur][kk][tm0 + 4];
            *(float4*)&b[0] = *(const float4*)&Bs[cur][kk][tn0];
            *(float4*)&b[4] = *(const float4*)&Bs[cur][kk][tn0 + 4];
            #pragma unroll
            for (int i = 0; i < 8; i++)
                #pragma unroll
                for (int j = 0; j < 8; j++)
                    acc[i][j] += a[i] * b[j];
        }

        if (more) {
            const int nxt = cur ^ 1;
            As[nxt][acol + 0][arow] = av_n.x;
            As[nxt][acol + 1][arow] = av_n.y;
            As[nxt][acol + 2][arow] = av_n.z;
            As[nxt][acol + 3][arow] = av_n.w;
            *(float4*)&Bs[nxt][b_r][b_c] = bv_n;
        }
        __syncthreads();
    }

    float bcache[8];
    #pragma unroll
    for (int j = 0; j < 8; j++) bcache[j] = bias[col0 + tn0 + j];
    #pragma unroll
    for (int i = 0; i < 8; i++) {
        int gr = row0 + tm0 + i;
        if (gr >= M) continue;
        float4 v0 = make_float4(acc[i][0] + bcache[0], acc[i][1] + bcache[1],
                                acc[i][2] + bcache[2], acc[i][3] + bcache[3]);
        float4 v1 = make_float4(acc[i][4] + bcache[4], acc[i][5] + bcache[5],
                                acc[i][6] + bcache[6], acc[i][7] + bcache[7]);
        *(float4*)&C[(size_t)gr * Nn + col0 + tn0]     = v0;
        *(float4*)&C[(size_t)gr * Nn + col0 + tn0 + 4] = v1;
    }
}

// ===== fused layer-1: per-node block, parallel scoring into smem =========
// Scores head-major s[h][SROW]; ssrc prescaled (src*256); chunks padded to
// multiples of 4 so phase C uses broadcast float4/int4 loads.
__global__ void __launch_bounds__(256)
fused1_kernel(const float* __restrict__ We, const float* __restrict__ att,
              const float* __restrict__ bias) {
    __shared__ __align__(16) float s[8 * SROW];
    __shared__ __align__(16) int   ssrc[SCAP];
    __shared__ float sea[SCAP];
    __shared__ float mh[8], sumh[8];

    const int j = blockIdx.x;
    const int cntj = g_cnt[j];
    const int dreal = min(cntj, CAPB);
    const int d = dreal + 1;               // + self loop
    const int off = j * CAPB;
    const int t = threadIdx.x;
    const int warp = t >> 5, lane = t & 31;
    const float eal = g_easum[j] / fmaxf((float)cntj, 1.0f);
    const int jofs = j * 256;

    if (t < 8) { mh[t] = -1e30f; sumh[t] = 0.f; }

    // phase-A per-lane constants (lane owns channels [8*lane, 8*lane+8))
    const int c0 = lane * 8;
    const float4 W0 = *(const float4*)&We[c0],  W1 = *(const float4*)&We[c0 + 4];
    const float4 A0 = *(const float4*)&att[c0], A1 = *(const float4*)&att[c0 + 4];
    const float4 xr0 = *(const float4*)&g_xr1[(size_t)jofs + c0];
    const float4 xr1 = *(const float4*)&g_xr1[(size_t)jofs + c0 + 4];

    float accv = 0.f;   // phase-C channel c = warp*32 + lane

    for (int cs = 0; cs < d; cs += SCAP) {
        const int cl = min(SCAP, d - cs);
        const int cl4 = (cl + 3) & ~3;
        for (int i = t; i < cl4; i += 256) {
            int ge = cs + i;
            if (ge < dreal) {
                ssrc[i] = g_bsrc[off + ge] << 8;   // *256 prescale (coalesced)
                sea[i]  = g_bea[off + ge];
            } else {
                ssrc[i] = jofs;                    // self loop / pad
                sea[i]  = eal;
            }
        }
        __syncthreads();

        // ---- phase A: parallel scoring, 2 edges in flight per warp ----
        for (int e = warp; e < cl; e += 16) {
            int e2 = e + 8;
            bool has2 = (e2 < cl);
            int   oA = ssrc[e];
            float vA = sea[e];
            int   oB = has2 ? ssrc[e2] : oA;
            float vB = has2 ? sea[e2] : vA;
            const float* xA = g_xl1 + oA + c0;
            const float* xB = g_xl1 + oB + c0;
            float4 a0 = *(const float4*)&xA[0];
            float4 a1 = *(const float4*)&xA[4];
            float4 b0 = *(const float4*)&xB[0];
            float4 b1 = *(const float4*)&xB[4];
            float pA, pB;
            {
                float a = a0.x + xr0.x + vA * W0.x; a = fmaxf(a,0.f) + 0.2f*fminf(a,0.f);
                float b = a0.y + xr0.y + vA * W0.y; b = fmaxf(b,0.f) + 0.2f*fminf(b,0.f);
                float c = a0.z + xr0.z + vA * W0.z; c = fmaxf(c,0.f) + 0.2f*fminf(c,0.f);
                float g = a0.w + xr0.w + vA * W0.w; g = fmaxf(g,0.f) + 0.2f*fminf(g,0.f);
                pA = a*A0.x + b*A0.y + c*A0.z + g*A0.w;
                a = a1.x + xr1.x + vA * W1.x; a = fmaxf(a,0.f) + 0.2f*fminf(a,0.f);
                b = a1.y + xr1.y + vA * W1.y; b = fmaxf(b,0.f) + 0.2f*fminf(b,0.f);
                c = a1.z + xr1.z + vA * W1.z; c = fmaxf(c,0.f) + 0.2f*fminf(c,0.f);
                g = a1.w + xr1.w + vA * W1.w; g = fmaxf(g,0.f) + 0.2f*fminf(g,0.f);
                pA += a*A1.x + b*A1.y + c*A1.z + g*A1.w;
            }
            {
                float a = b0.x + xr0.x + vB * W0.x; a = fmaxf(a,0.f) + 0.2f*fminf(a,0.f);
                float b = b0.y + xr0.y + vB * W0.y; b = fmaxf(b,0.f) + 0.2f*fminf(b,0.f);
                float c = b0.z + xr0.z + vB * W0.z; c = fmaxf(c,0.f) + 0.2f*fminf(c,0.f);
                float g = b0.w + xr0.w + vB * W0.w; g = fmaxf(g,0.f) + 0.2f*fminf(g,0.f);
                pB = a*A0.x + b*A0.y + c*A0.z + g*A0.w;
                a = b1.x + xr1.x + vB * W1.x; a = fmaxf(a,0.f) + 0.2f*fminf(a,0.f);
                b = b1.y + xr1.y + vB * W1.y; b = fmaxf(b,0.f) + 0.2f*fminf(b,0.f);
                c = b1.z + xr1.z + vB * W1.z; c = fmaxf(c,0.f) + 0.2f*fminf(c,0.f);
                g = b1.w + xr1.w + vB * W1.w; g = fmaxf(g,0.f) + 0.2f*fminf(g,0.f);
                pB += a*A1.x + b*A1.y + c*A1.z + g*A1.w;
            }
            pA += __shfl_xor_sync(0xffffffffu, pA, 1);
            pB += __shfl_xor_sync(0xffffffffu, pB, 1);
            pA += __shfl_xor_sync(0xffffffffu, pA, 2);
            pB += __shfl_xor_sync(0xffffffffu, pB, 2);
            if ((lane & 3) == 0) {
                s[(lane >> 2) * SROW + e] = pA;
                if (has2) s[(lane >> 2) * SROW + e2] = pB;
            }
        }
        __syncthreads();

        // ---- phase B: per-head chunk max/sum, scores -> weights --------
        const int h = warp;
        float* sw = s + h * SROW;
        float cmx = -1e30f;
        for (int e = lane; e < cl; e += 32) cmx = fmaxf(cmx, sw[e]);
        #pragma unroll
        for (int o = 16; o; o >>= 1)
            cmx = fmaxf(cmx, __shfl_xor_sync(0xffffffffu, cmx, o));
        float m_o = mh[h];
        float nm = fmaxf(m_o, cmx);
        float csum = 0.f;
        for (int e = lane; e < cl; e += 32) {
            float w = __expf(sw[e] - nm);
            sw[e] = w;
            csum += w;
        }
        for (int e = cl + lane; e < cl4; e += 32) sw[e] = 0.f;  // pad
        #pragma unroll
        for (int o = 16; o; o >>= 1) csum += __shfl_xor_sync(0xffffffffu, csum, o);
        float fac = __expf(m_o - nm);
        if (lane == 0) { sumh[h] = sumh[h] * fac + csum; mh[h] = nm; }
        __syncwarp();

        // ---- phase C: vectorized gather (broadcast float4/int4) --------
        const float* xbase = g_xl1 + h * 32 + lane;
        float p0 = 0.f, p1 = 0.f, p2 = 0.f, p3 = 0.f;
        for (int e = 0; e < cl4; e += 4) {
            float4 wv = *(const float4*)&sw[e];
            int4   iv = *(const int4*)&ssrc[e];
            p0 += wv.x * xbase[iv.x];
            p1 += wv.y * xbase[iv.y];
            p2 += wv.z * xbase[iv.z];
            p3 += wv.w * xbase[iv.w];
        }
        accv = accv * fac + ((p0 + p1) + (p2 + p3));
        __syncthreads();
    }

    const int h = warp;
    float inv = 1.0f / (sumh[h] + 1e-16f);
    int c = h * 32 + lane;
    g_h1[(size_t)j * 256 + c] = fmaxf(accv * inv + bias[c], 0.f);
}

// ===== fused layer-2: per-node block (128 thr), single head ==============
__global__ void __launch_bounds__(128)
fused2_kernel(const float* __restrict__ We, const float* __restrict__ att,
              const float* __restrict__ bias) {
    __shared__ __align__(16) float s[SCAP];
    __shared__ __align__(16) int   ssrc[SCAP];
    __shared__ float sea[SCAP];
    __shared__ float red[4];
    __shared__ float m_run_s, sum_run_s, nm_s, fac_s;

    const int j = blockIdx.x;
    const int cntj = g_cnt[j];
    const int dreal = min(cntj, CAPB);
    const int d = dreal + 1;               // + self loop
    const int off = j * CAPB;
    const int t = threadIdx.x;
    const int warp = t >> 5, lane = t & 31;
    const float eal = g_easum[j] / fmaxf((float)cntj, 1.0f);
    const int jofs = j * 128;

    if (t == 0) { m_run_s = -1e30f; sum_run_s = 0.f; }

    const int c0 = lane * 4;
    const float4 Wv = *(const float4*)&We[c0];
    const float4 Av = *(const float4*)&att[c0];
    const float4 xr = *(const float4*)&g_xr2[(size_t)jofs + c0];

    float accv = 0.f;   // channel = t

    for (int cs = 0; cs < d; cs += SCAP) {
        const int cl = min(SCAP, d - cs);
        const int cl4 = (cl + 3) & ~3;
        for (int i = t; i < cl4; i += 128) {
            int ge = cs + i;
            if (ge < dreal) {
                ssrc[i] = g_bsrc[off + ge] << 7;   // *128 prescale (coalesced)
                sea[i]  = g_bea[off + ge];
            } else {
                ssrc[i] = jofs;
                sea[i]  = eal;
            }
        }
        __syncthreads();

        // phase A: warp per edge (strided 4), 2 in flight
        for (int e = warp; e < cl; e += 8) {
            int e2 = e + 4;
            bool has2 = (e2 < cl);
            int   oA = ssrc[e];
            float vA = sea[e];
            int   oB = has2 ? ssrc[e2] : oA;
            float vB = has2 ? sea[e2] : vA;
            float4 lA = *(const float4*)&g_xl2[oA + c0];
            float4 lB = *(const float4*)&g_xl2[oB + c0];
            float pA, pB;
            {
                float a = lA.x + xr.x + vA * Wv.x; a = fmaxf(a,0.f) + 0.2f*fminf(a,0.f);
                float b = lA.y + xr.y + vA * Wv.y; b = fmaxf(b,0.f) + 0.2f*fminf(b,0.f);
                float c = lA.z + xr.z + vA * Wv.z; c = fmaxf(c,0.f) + 0.2f*fminf(c,0.f);
                float g = lA.w + xr.w + vA * Wv.w; g = fmaxf(g,0.f) + 0.2f*fminf(g,0.f);
                pA = a*Av.x + b*Av.y + c*Av.z + g*Av.w;
            }
            {
                float a = lB.x + xr.x + vB * Wv.x; a = fmaxf(a,0.f) + 0.2f*fminf(a,0.f);
                float b = lB.y + xr.y + vB * Wv.y; b = fmaxf(b,0.f) + 0.2f*fminf(b,0.f);
                float c = lB.z + xr.z + vB * Wv.z; c = fmaxf(c,0.f) + 0.2f*fminf(c,0.f);
                float g = lB.w + xr.w + vB * Wv.w; g = fmaxf(g,0.f) + 0.2f*fminf(g,0.f);
                pB = a*Av.x + b*Av.y + c*Av.z + g*Av.w;
            }
            #pragma unroll
            for (int o = 16; o; o >>= 1) {
                pA += __shfl_xor_sync(0xffffffffu, pA, o);
                pB += __shfl_xor_sync(0xffffffffu, pB, o);
            }
            if (lane == 0) {
                s[e] = pA;
                if (has2) s[e2] = pB;
            }
        }
        __syncthreads();

        // phase B: block max
        float cmx = -1e30f;
        for (int e = t; e < cl; e += 128) cmx = fmaxf(cmx, s[e]);
        #pragma unroll
        for (int o = 16; o; o >>= 1)
            cmx = fmaxf(cmx, __shfl_xor_sync(0xffffffffu, cmx, o));
        if (lane == 0) red[warp] = cmx;
        __syncthreads();
        if (t == 0) {
            float M = fmaxf(fmaxf(red[0], red[1]), fmaxf(red[2], red[3]));
            float nm = fmaxf(m_run_s, M);
            nm_s = nm;
            fac_s = __expf(m_run_s - nm);
            m_run_s = nm;
        }
        __syncthreads();
        float nm = nm_s;
        // weights in place + block sum (+ zero pad)
        float csum = 0.f;
        for (int e = t; e < cl; e += 128) {
            float w = __expf(s[e] - nm);
            s[e] = w;
            csum += w;
        }
        for (int e = cl + t; e < cl4; e += 128) s[e] = 0.f;
        #pragma unroll
        for (int o = 16; o; o >>= 1) csum += __shfl_xor_sync(0xffffffffu, csum, o);
        if (lane == 0) red[warp] = csum;
        __syncthreads();
        if (t == 0)
            sum_run_s = sum_run_s * fac_s + (red[0] + red[1] + red[2] + red[3]);
        float fac = fac_s;
        __syncthreads();   // weights visible to all warps before gather

        // phase C: vectorized gather (broadcast float4/int4), channel = t
        const float* xbase = g_xl2 + t;
        float p0 = 0.f, p1 = 0.f, p2 = 0.f, p3 = 0.f;
        for (int e = 0; e < cl4; e += 4) {
            float4 wv = *(const float4*)&s[e];
            int4   iv = *(const int4*)&ssrc[e];
            p0 += wv.x * xbase[iv.x];
            p1 += wv.y * xbase[iv.y];
            p2 += wv.z * xbase[iv.z];
            p3 += wv.w * xbase[iv.w];
        }
        accv = accv * fac + ((p0 + p1) + (p2 + p3));
        __syncthreads();
    }

    float inv = 1.0f / (sum_run_s + 1e-16f);
    float val = fmaxf(accv * inv + bias[t], 0.f);
    atomicAdd(&g_pool[t], val);
}

// ---------------- final: mean, softmax, sigmoid(alpha) -------------------
__global__ void final_kernel(const float* __restrict__ alpha_in,
                             float* __restrict__ out, int out_size, float invN) {
    __shared__ float sh[128];
    int t = threadIdx.x;
    float v = g_pool[t] * invN;
    sh[t] = v;
    __syncthreads();
    for (int o = 64; o; o >>= 1) {
        if (t < o) sh[t] = fmaxf(sh[t], sh[t + o]);
        __syncthreads();
    }
    float mx = sh[0];
    __syncthreads();
    float e = __expf(v - mx);
    sh[t] = e;
    __syncthreads();
    for (int o = 64; o; o >>= 1) {
        if (t < o) sh[t] += sh[t + o];
        __syncthreads();
    }
    float s = sh[0];
    out[t] = e / s;
    if (t == 0 && out_size > 128)
        out[128] = 1.0f / (1.0f + __expf(-alpha_in[0]));
}

// -------------------------------------------------------------------------
extern "C" void kernel_launch(void* const* d_in, const int* in_sizes, int n_in,
                              void* d_out, int out_size) {
    (void)n_in;
    const float* x     = (const float*)d_in[0];
    const int*   eidx  = (const int*)d_in[1];   // int32 or int64 (detected)
    const float* ea    = (const float*)d_in[2];
    const float* W1l   = (const float*)d_in[3];
    const float* b1l   = (const float*)d_in[4];
    const float* W1r   = (const float*)d_in[5];
    const float* b1r   = (const float*)d_in[6];
    const float* We1   = (const float*)d_in[7];
    const float* att1  = (const float*)d_in[8];
    const float* bias1 = (const float*)d_in[9];
    const float* W2l   = (const float*)d_in[10];
    const float* b2l   = (const float*)d_in[11];
    const float* W2r   = (const float*)d_in[12];
    const float* b2r   = (const float*)d_in[13];
    const float* We2   = (const float*)d_in[14];
    const float* att2  = (const float*)d_in[15];
    const float* bias2 = (const float*)d_in[16];
    const float* alpha = (const float*)d_in[17];
    float* out = (float*)d_out;

    int N = in_sizes[0] / 128;
    if (N > NMAX) N = NMAX;
    int E = in_sizes[1] / 2;
    if (E > EMAX) E = EMAX;

    int mb = (N + 127) / 128;

    detect_init_kernel<<<(N + 255) / 256, 256>>>(eidx, N, E);   // 1
    gemm_bias_dual<<<dim3(mb, 2, 2), 256>>>(x, -1, W1l, b1l, 0, W1r, b1r, 1,
                                            N, 128, 256);      // 2
    extract_kernel<<<(E + 255) / 256, 256>>>(eidx, ea, E);      // 3

    // layer 1: fused score+softmax+aggregate (per node) — profiled slot 4
    fused1_kernel<<<N, 256>>>(We1, att1, bias1);                // 4

    // layer 2
    gemm_bias_dual<<<dim3(mb, 1, 2), 256>>>(nullptr, 2, W2l, b2l, 3, W2r, b2r, 4,
                                            N, 256, 128);      // 5
    fused2_kernel<<<N, 128>>>(We2, att2, bias2);                // 6

    // pooled softmax + sigmoid(alpha)
    final_kernel<<<1, 128>>>(alpha, out, out_size, 1.0f / (float)N); // 7
}